// round 11
// baseline (speedup 1.0000x reference)
#include <cuda_runtime.h>
#include <cuda_bf16.h>

// LIF recurrent scan, v8: single kernel; self-zeroing output; 1 barrier/chunk.
//
// 1 CTA per batch row, 1024 threads, 1 neuron/thread, state in registers for
// all T steps. Chunks of CHUNK=10 steps run speculatively (no act, no stores,
// no barriers); a register max-tracker detects any state>=1.0 -> exact replay
// with per-step barriers (rare). Next chunk's x prefetched into regs (MLP=10).
//
// v8 changes (from R10 evidence: fill kernel ~25us pure overhead; scan has
// idle store bw + removable sync machinery):
//  - fill kernel deleted; each chunk zeroes the NEXT chunk's 40KB out slice
//    with float4 stores (ordering via the per-chunk barrier).
//  - per-step FSETP+@P STS detector -> 1 FMNMX/step + one STS per chunk.
//  - 3-slot rotating spike lists AND flags -> ONE __syncthreads per chunk
//    (slot written at c, read post-BAR(c), reset at c+2 pre-BAR(c+2):
//    all conflicting accesses separated by a barrier).

#define N_NEU   1024
#define THREADS 1024
#define CHUNK   10           // even; T=1000 = 100 chunks

__device__ __forceinline__ float rank_k(const int* __restrict__ idx,
                                        const float* __restrict__ val,
                                        int c, float rec,
                                        const float* __restrict__ wrow) {
    for (int k = 0; k < c; k++)
        rec = fmaf(val[k], wrow[idx[k]], rec);
    return rec;
}

__global__ __launch_bounds__(THREADS, 1)
void lif_recurrent_kernel(const float* __restrict__ x,     // [B, T, N]
                          const float* __restrict__ W,     // [N, N] (out, in)
                          const float* __restrict__ bias,  // [N]
                          float* __restrict__ out,         // [B, T, N]
                          int T)
{
    const int b   = blockIdx.x;
    const int tid = threadIdx.x;

    __shared__ int   s_idx[3][N_NEU];
    __shared__ float s_val[3][N_NEU];
    __shared__ int   s_cnt[3];
    __shared__ int   s_flag[3];
    if (tid < 3) { s_cnt[tid] = 0; s_flag[tid] = 0; }

    float state = 0.0f;
    const float brec  = bias[tid];
    const float* wrow = W + (size_t)tid * N_NEU;

    const float* xb = x   + (size_t)b * T * N_NEU + tid;
    float*       op = out + (size_t)b * T * N_NEU + tid;
    float4*      oz = reinterpret_cast<float4*>(out + (size_t)b * T * N_NEU);

    const float ALPHA = 0.9f;
    const float OMA   = 1.0f - 0.9f;
    const int   ZPC   = CHUNK * N_NEU / 4;       // float4s per chunk region

    // zero chunk-0's output region before the first barrier
#pragma unroll
    for (int i = 0; i < 3; i++) {
        const int k = tid + i * THREADS;
        if (k < ZPC) oz[k] = make_float4(0.f, 0.f, 0.f, 0.f);
    }

    // preload chunk 0 x
    float xA[CHUNK], xB[CHUNK];
#pragma unroll
    for (int s = 0; s < CHUNK; s++)
        xA[s] = xb[(size_t)min(s, T - 1) * N_NEU];

    __syncthreads();      // smem init + region-0 zero visible

    int w = 0, r = 2, z = 1;   // chunk ci: w=ci%3, r=(ci+2)%3, z=(ci+1)%3

    for (int tc = 0; tc < T; tc += CHUNK) {
        float* xcur = ((tc / CHUNK) & 1) ? xB : xA;
        float* xnxt = ((tc / CHUNK) & 1) ? xA : xB;

        // ---- prefetch next chunk's x (MLP = CHUNK) ----
#pragma unroll
        for (int s = 0; s < CHUNK; s++) {
            const int tp = min(tc + CHUNK + s, T - 1);
            xnxt[s] = xb[(size_t)tp * N_NEU];
        }

        // ---- zero next chunk's output region (float4, ~2.5 per thread) ----
        if (tc + CHUNK < T) {
            float4* ozr = oz + (size_t)(tc + CHUNK) * (N_NEU / 4);
#pragma unroll
            for (int i = 0; i < 3; i++) {
                const int k = tid + i * THREADS;
                if (k < ZPC) ozr[k] = make_float4(0.f, 0.f, 0.f, 0.f);
            }
        }

        const int   c_prev = s_cnt[r];
        const float snap   = state;
        float mx = -1e30f;

        // -------- fast speculative pass: no stores, no barriers --------
#pragma unroll
        for (int s = 0; s < CHUNK - 1; s++) {
            float rec = brec;
            if (s == 0) rec = rank_k(s_idx[r], s_val[r], c_prev, brec, wrow);

            mx = fmaxf(mx, state);                 // spike detector (register)

            const float tot = xcur[s] + rec;
            state = (state - 0.0f) * ALPHA + OMA * tot;
        }
        // ---- last step: exact act (its spikes feed the next chunk) ----
        {
            const float sv  = state;
            const float act = (sv > 0.0f) ? floorf(sv) : 0.0f;
            if (act != 0.0f) {                      // rare
                const int p = atomicAdd(&s_cnt[w], 1);
                s_idx[w][p] = tid;
                s_val[w][p] = act;
                op[(size_t)(tc + CHUNK - 1) * N_NEU] = act;
            }
            const float tot = xcur[CHUNK - 1] + brec;
            state = (sv - act) * ALPHA + OMA * tot;
        }

        if (mx >= 1.0f) s_flag[w] = 1;              // one STS per chunk, rare
        if (tid == 0) { s_cnt[z] = 0; s_flag[z] = 0; }

        __syncthreads();                            // the ONE barrier per chunk

        const int f = s_flag[w];
        if (f) {
            // -------- rollback: exact replay with per-step barriers --------
            state = snap;
            if (tid == 0) s_cnt[w] = 0;             // discard spec pushes
            __syncthreads();

            int Lr = r, Lw = z;                     // z was zeroed pre-BAR
#pragma unroll 1
            for (int s = 0; s < CHUNK; s++) {
                const int c = s_cnt[Lr];
                const float rec = rank_k(s_idx[Lr], s_val[Lr], c, brec, wrow);

                const float sv  = state;
                const float act = (sv > 0.0f) ? floorf(sv) : 0.0f;
                const int dst = (s == CHUNK - 1) ? w : Lw;
                if (act != 0.0f) {
                    const int p = atomicAdd(&s_cnt[dst], 1);
                    s_idx[dst][p] = tid;
                    s_val[dst][p] = act;
                }
                // nonzero: always store; last step: store even zero to scrub a
                // possible stale speculative nonzero from this thread.
                if (act != 0.0f || s == CHUNK - 1)
                    op[(size_t)(tc + s) * N_NEU] = act;

                const float tot = xcur[s] + rec;
                state = (sv - act) * ALPHA + OMA * tot;

                __syncthreads();
                if (tid == 0) s_cnt[Lr] = 0;
                __syncthreads();
                const int tmp = Lr; Lr = dst; Lw = tmp;
            }
            // CHUNK even -> both scratch lists (r, z) end zeroed; final-step
            // spikes live in w; flags: s_flag[w]==1 but it is reset at chunk
            // ci+2 (as that chunk's z) before it is next read at ci+3.
        }

        // rotate: next chunk's (w,r,z) = (z, w, r)
        const int t0 = w; w = z; z = r; r = t0;
    }
}

extern "C" void kernel_launch(void* const* d_in, const int* in_sizes, int n_in,
                              void* d_out, int out_size)
{
    const float* x    = (const float*)d_in[0];   // input_current [B, T, N]
    const float* W    = (const float*)d_in[1];   // w_rec [N, N]
    const float* bias = (const float*)d_in[2];   // b_rec [N]
    float* out = (float*)d_out;

    const int N = in_sizes[2];                   // 1024
    const int T = 1000;
    const int B = in_sizes[0] / (T * N);         // 32

    lif_recurrent_kernel<<<B, THREADS>>>(x, W, bias, out, T);
}

// round 12
// speedup vs baseline: 1.5756x; 1.5756x over previous
#include <cuda_runtime.h>
#include <cuda_bf16.h>

// LIF recurrent scan, v9 = v7 (two-kernel: full-chip zero-fill + store-free
// scan) + issue-side micro-opts.
//
// Evidence recap: scan is bound on its 32 SMs (~14 issues/thread/step at
// issue~45%); the 128MB output-zeroing MUST run on all 148 SMs (v8 folded it
// into the scan and regressed 2x). v9 reverts to the v7 structure and cuts
// per-step issues: chunk-base-pointer prefetch with immediate offsets
// (removes ~10 IMAD+IMNMX per chunk) and a register max-tracker spike
// detector (1 FMNMX/step + one STS/chunk instead of FSETP+@P STS per step).
//
// Scan: 1 CTA/batch row, 1024 threads, 1 neuron/thread, state in registers
// for all T steps. CHUNK=10 steps run speculatively (no act, no stores, no
// barriers); mx>=1.0 -> exact replay with per-step barriers (rare). Next
// chunk's x prefetched into registers (MLP=10). Output pre-zeroed, so only
// nonzero acts are ever stored.

#define N_NEU   1024
#define THREADS 1024
#define CHUNK   10           // even; T=1000 = 100 chunks

__global__ void fill_zero_kernel(float4* __restrict__ p, int n4) {
    const int stride = gridDim.x * blockDim.x;
    for (int i = blockIdx.x * blockDim.x + threadIdx.x; i < n4; i += stride)
        p[i] = make_float4(0.f, 0.f, 0.f, 0.f);
}

__global__ __launch_bounds__(THREADS, 1)
void lif_recurrent_kernel(const float* __restrict__ x,     // [B, T, N]
                          const float* __restrict__ W,     // [N, N] (out, in)
                          const float* __restrict__ bias,  // [N]
                          float* __restrict__ out,         // [B, T, N]
                          int T)
{
    const int b   = blockIdx.x;
    const int tid = threadIdx.x;

    __shared__ int   s_idx[2][N_NEU];
    __shared__ float s_val[2][N_NEU];
    __shared__ int   s_cnt[2];
    __shared__ int   s_flag;
    if (tid < 2) s_cnt[tid] = 0;
    if (tid == 0) s_flag = 0;
    __syncthreads();

    float state = 0.0f;
    const float brec  = bias[tid];
    const float* wrow = W + (size_t)tid * N_NEU;

    const float* xb = x   + (size_t)b * T * N_NEU + tid;
    float*       op = out + (size_t)b * T * N_NEU + tid;

    const float ALPHA = 0.9f;
    const float OMA   = 1.0f - 0.9f;

    // preload chunk 0 into buffer A (immediate offsets off xb)
    float xA[CHUNK], xB[CHUNK];
#pragma unroll
    for (int s = 0; s < CHUNK; s++)
        xA[s] = xb[s * N_NEU];

    int pb = 0, qb = 1;

    for (int tc = 0; tc < T; tc += CHUNK) {
        float* xcur = ((tc / CHUNK) & 1) ? xB : xA;
        float* xnxt = ((tc / CHUNK) & 1) ? xA : xB;

        // issue the (usually-zero) list count load early; overlaps the LDGs
        const int c_prev = s_cnt[pb];

        // ---- prefetch next chunk: one clamped base, immediate offsets ----
        {
            const float* xp = xb + (size_t)min(tc + CHUNK, T - CHUNK) * N_NEU;
#pragma unroll
            for (int s = 0; s < CHUNK; s++)
                xnxt[s] = xp[s * N_NEU];          // LDG with imm offset, MLP=10
        }

        const float snap = state;
        float mx = 0.0f;

        // -------- fast speculative pass: no stores, no barriers, no act ----
#pragma unroll
        for (int s = 0; s < CHUNK - 1; s++) {
            float rec = brec;
            if (s == 0) {                         // compile-time branch
                for (int k = 0; k < c_prev; k++)
                    rec = fmaf(s_val[pb][k], wrow[s_idx[pb][k]], rec);
            }

            mx = fmaxf(mx, state);                // detector: 1 FMNMX/step

            const float tot = xcur[s] + rec;
            state = (state - 0.0f) * ALPHA + OMA * tot;
        }

        // ---- last step of chunk: exact act (spikes feed the next chunk) ----
        {
            const float sv  = state;
            const float act = (sv > 0.0f) ? floorf(sv) : 0.0f;
            if (act != 0.0f) {                    // rare: push + store
                const int p = atomicAdd(&s_cnt[qb], 1);
                s_idx[qb][p] = tid;
                s_val[qb][p] = act;
                op[(size_t)(tc + CHUNK - 1) * N_NEU] = act;
            }
            const float tot = xcur[CHUNK - 1] + brec;   // rec = bias for s > 0
            state = (sv - act) * ALPHA + OMA * tot;
        }

        if (mx >= 1.0f) s_flag = 1;               // one STS per chunk, rare

        __syncthreads();                    // B1: flag & pushes visible
        const int f = s_flag;
        if (tid == 0 && !f) s_cnt[pb] = 0;  // retire prev list (commit only)
        __syncthreads();                    // B2: flag consumed by all

        if (f) {
            // -------- rollback: exact replay with per-step barriers --------
            state = snap;
            if (tid == 0) { s_cnt[qb] = 0; s_flag = 0; }
            __syncthreads();

            int rb = pb, wb = qb;
#pragma unroll 1
            for (int s = 0; s < CHUNK; s++) {
                const int t = tc + s;
                const int c = s_cnt[rb];
                const float xv = xb[(size_t)t * N_NEU];

                float rec = brec;
                for (int k = 0; k < c; k++)
                    rec = fmaf(s_val[rb][k], wrow[s_idx[rb][k]], rec);

                const float sv  = state;
                const float act = (sv > 0.0f) ? floorf(sv) : 0.0f;
                if (act != 0.0f) {
                    const int p = atomicAdd(&s_cnt[wb], 1);
                    s_idx[wb][p] = tid;
                    s_val[wb][p] = act;
                }
                // nonzero: always store; last step: store even zero to scrub
                // a possible stale speculative nonzero from this thread.
                if (act != 0.0f || s == CHUNK - 1)
                    op[(size_t)t * N_NEU] = act;

                const float tot = xv + rec;
                state = (sv - act) * ALPHA + OMA * tot;

                __syncthreads();
                if (tid == 0) s_cnt[rb] = 0;
                __syncthreads();
                const int tmp = rb; rb = wb; wb = tmp;
            }
            pb = rb; qb = wb;   // CHUNK even: last-step spikes in pb, qb zeroed
        } else {
            const int tmp = pb; pb = qb; qb = tmp;
        }
    }
}

extern "C" void kernel_launch(void* const* d_in, const int* in_sizes, int n_in,
                              void* d_out, int out_size)
{
    const float* x    = (const float*)d_in[0];   // input_current [B, T, N]
    const float* W    = (const float*)d_in[1];   // w_rec [N, N]
    const float* bias = (const float*)d_in[2];   // b_rec [N]
    float* out = (float*)d_out;

    const int N = in_sizes[2];                   // 1024
    const int T = 1000;
    const int B = in_sizes[0] / (T * N);         // 32

    // 1) zero the output at full-chip HBM rate (out is poisoned by harness)
    fill_zero_kernel<<<1184, 256>>>((float4*)out, out_size / 4);

    // 2) scan kernel: stores only nonzero spikes
    lif_recurrent_kernel<<<B, THREADS>>>(x, W, bias, out, T);
}